// round 1
// baseline (speedup 1.0000x reference)
#include <cuda_runtime.h>
#include <math.h>

// Problem constants (fixed shapes for this problem instance)
#define Zc 512
#define Hc 256
#define NMAX 20000
#define BMAX 32
#define DPB 8      // docs per block in doc kernel
#define SDOCS 4    // docs per block in score kernel
#define KMAX 8

// Scratch (no allocations allowed anywhere)
__device__ float g_qb[BMAX * Hc];                 // qa + b1, [B,H]
__device__ float g_da[(size_t)NMAX * Hc];         // d_t @ W1[H:], [N,H]
__device__ float g_scores[(size_t)BMAX * NMAX];   // scaled scores [B,N]

__device__ __forceinline__ float gelu_f(float x) {
    // exact gelu: 0.5*x*(1+erf(x/sqrt(2)))
    return 0.5f * x * (1.0f + erff(x * 0.70710678118654752440f));
}

// ---------------------------------------------------------------------------
// Kernel 1: query path.  grid = B, block = 256 (one thread per h)
// q_t = LN(gelu(q@Wq + bq)); qb = q_t@W1[:H] + b1
// ---------------------------------------------------------------------------
__global__ __launch_bounds__(256) void query_kernel(
    const float* __restrict__ q, const float* __restrict__ Wq,
    const float* __restrict__ bq, const float* __restrict__ lnw,
    const float* __restrict__ lnb, const float* __restrict__ W1,
    const float* __restrict__ b1)
{
    __shared__ float xq[Zc];
    __shared__ float qt[Hc];
    __shared__ float red[18];
    int b = blockIdx.x, t = threadIdx.x;
    const float* row = q + (size_t)b * Zc;
    for (int i = t; i < Zc; i += 256) xq[i] = row[i];
    __syncthreads();

    float acc = bq[t];
    #pragma unroll 8
    for (int z = 0; z < Zc; z++) acc = fmaf(xq[z], Wq[z * Hc + t], acc);
    float g = gelu_f(acc);

    // block LN over 256 values
    float s = g, s2 = g * g;
    #pragma unroll
    for (int o = 16; o; o >>= 1) {
        s  += __shfl_down_sync(0xffffffffu, s, o);
        s2 += __shfl_down_sync(0xffffffffu, s2, o);
    }
    if ((t & 31) == 0) { red[t >> 5] = s; red[8 + (t >> 5)] = s2; }
    __syncthreads();
    if (t == 0) {
        float S = 0.f, S2 = 0.f;
        for (int w = 0; w < 8; w++) { S += red[w]; S2 += red[8 + w]; }
        float mu = S / (float)Hc;
        red[16] = mu;
        red[17] = S2 / (float)Hc - mu * mu;
    }
    __syncthreads();
    float mu = red[16], var = red[17];
    float v = (g - mu) * rsqrtf(var + 1e-5f) * lnw[t] + lnb[t];
    qt[t] = v;
    __syncthreads();

    float a2 = b1[t];  // fold b1 here
    #pragma unroll 8
    for (int j = 0; j < Hc; j++) a2 = fmaf(qt[j], W1[j * Hc + t], a2);
    g_qb[b * Hc + t] = a2;
}

// ---------------------------------------------------------------------------
// Kernel 2: doc path, fused. grid = N/DPB, block = 256.
// Thread layout: hg = tid&63 owns h = 4*hg..4*hg+3 (float4), ds = tid>>6 owns
// docs {ds, ds+4}.  d_t never leaves smem; only da is written.
// ---------------------------------------------------------------------------
__global__ __launch_bounds__(256) void doc_kernel(
    const float* __restrict__ docs, const float* __restrict__ Wd,
    const float* __restrict__ bd, const float* __restrict__ lnw,
    const float* __restrict__ lnb, const float* __restrict__ W1, int N)
{
    __shared__ float xs[DPB][Zc];   // 16 KB: raw doc rows
    __shared__ float dt[DPB][Hc];   // 8 KB: post-gelu / post-LN activations
    int t = threadIdx.x;
    int hg = t & 63, ds = t >> 6;
    int docBase = blockIdx.x * DPB;

    // cooperative vectorized load of 8 doc rows
    const float4* src = (const float4*)(docs + (size_t)docBase * Zc);
    float4* dstp = (float4*)&xs[0][0];
    #pragma unroll
    for (int i = t; i < DPB * Zc / 4; i += 256) dstp[i] = src[i];
    __syncthreads();

    // GEMM1: d = x @ Wd + bd  (each thread: 4h x 2docs)
    float4 bd4 = *(const float4*)&bd[hg * 4];
    float4 a0 = bd4, a1 = bd4;
    for (int z = 0; z < Zc; z += 4) {
        float4 xa = *(const float4*)&xs[ds][z];
        float4 xb = *(const float4*)&xs[ds + 4][z];
        float xav[4] = {xa.x, xa.y, xa.z, xa.w};
        float xbv[4] = {xb.x, xb.y, xb.z, xb.w};
        #pragma unroll
        for (int u = 0; u < 4; u++) {
            float4 w = *(const float4*)&Wd[(size_t)(z + u) * Hc + hg * 4];
            a0.x = fmaf(w.x, xav[u], a0.x); a0.y = fmaf(w.y, xav[u], a0.y);
            a0.z = fmaf(w.z, xav[u], a0.z); a0.w = fmaf(w.w, xav[u], a0.w);
            a1.x = fmaf(w.x, xbv[u], a1.x); a1.y = fmaf(w.y, xbv[u], a1.y);
            a1.z = fmaf(w.z, xbv[u], a1.z); a1.w = fmaf(w.w, xbv[u], a1.w);
        }
    }
    // gelu -> dt
    dt[ds][hg * 4 + 0] = gelu_f(a0.x);
    dt[ds][hg * 4 + 1] = gelu_f(a0.y);
    dt[ds][hg * 4 + 2] = gelu_f(a0.z);
    dt[ds][hg * 4 + 3] = gelu_f(a0.w);
    dt[ds + 4][hg * 4 + 0] = gelu_f(a1.x);
    dt[ds + 4][hg * 4 + 1] = gelu_f(a1.y);
    dt[ds + 4][hg * 4 + 2] = gelu_f(a1.z);
    dt[ds + 4][hg * 4 + 3] = gelu_f(a1.w);
    __syncthreads();

    // LayerNorm per doc: warp w normalizes doc w
    {
        int wid = t >> 5, lane = t & 31;
        float* r = dt[wid];
        float s = 0.f, s2 = 0.f;
        #pragma unroll
        for (int j = lane; j < Hc; j += 32) { float v = r[j]; s += v; s2 += v * v; }
        #pragma unroll
        for (int o = 16; o; o >>= 1) {
            s  += __shfl_xor_sync(0xffffffffu, s, o);
            s2 += __shfl_xor_sync(0xffffffffu, s2, o);
        }
        float mu = s / (float)Hc;
        float rin = rsqrtf(s2 / (float)Hc - mu * mu + 1e-5f);
        #pragma unroll
        for (int j = lane; j < Hc; j += 32)
            r[j] = (r[j] - mu) * rin * lnw[j] + lnb[j];
    }
    __syncthreads();

    // GEMM2: da = dt @ W1[H:2H]
    float4 c0 = make_float4(0.f, 0.f, 0.f, 0.f), c1 = c0;
    for (int j = 0; j < Hc; j += 4) {
        float4 xa = *(const float4*)&dt[ds][j];
        float4 xb = *(const float4*)&dt[ds + 4][j];
        float xav[4] = {xa.x, xa.y, xa.z, xa.w};
        float xbv[4] = {xb.x, xb.y, xb.z, xb.w};
        #pragma unroll
        for (int u = 0; u < 4; u++) {
            float4 w = *(const float4*)&W1[(size_t)(Hc + j + u) * Hc + hg * 4];
            c0.x = fmaf(w.x, xav[u], c0.x); c0.y = fmaf(w.y, xav[u], c0.y);
            c0.z = fmaf(w.z, xav[u], c0.z); c0.w = fmaf(w.w, xav[u], c0.w);
            c1.x = fmaf(w.x, xbv[u], c1.x); c1.y = fmaf(w.y, xbv[u], c1.y);
            c1.z = fmaf(w.z, xbv[u], c1.z); c1.w = fmaf(w.w, xbv[u], c1.w);
        }
    }
    ((float4*)&g_da[(size_t)(docBase + ds) * Hc])[hg] = c0;
    ((float4*)&g_da[(size_t)(docBase + ds + 4) * Hc])[hg] = c1;
}

// ---------------------------------------------------------------------------
// Kernel 3: pairwise scoring.  grid = N/SDOCS, block = 256.
// raw[b,n] = sum_h gelu(qb[b,h] + da[n,h]) * W2[h] + b2;  scaled by 1/(|T|+eps)
// Warp w handles b in {w, w+8, w+16, w+24}; lane owns 8 h-slots (register-
// resident da and W2, 4x reuse across b).
// ---------------------------------------------------------------------------
__global__ __launch_bounds__(256) void score_kernel(
    const float* __restrict__ W2, const float* __restrict__ b2,
    const float* __restrict__ temp, int N)
{
    __shared__ float qbs[BMAX * Hc];   // 32 KB
    __shared__ float das[SDOCS][Hc];
    __shared__ float w2s[Hc];
    int t = threadIdx.x;

    const float4* qsrc = (const float4*)g_qb;
    float4* qdst = (float4*)qbs;
    #pragma unroll
    for (int i = t; i < BMAX * Hc / 4; i += 256) qdst[i] = qsrc[i];
    w2s[t] = W2[t];
    int docBase = blockIdx.x * SDOCS;
    ((float4*)&das[0][0])[t] = ((const float4*)(g_da + (size_t)docBase * Hc))[t];
    __syncthreads();

    float invt = 1.0f / (fabsf(temp[0]) + 1e-8f);
    float bb = b2[0];
    int w = t >> 5, lane = t & 31;

    float wv[8];
    #pragma unroll
    for (int j = 0; j < 8; j++) wv[j] = w2s[lane + 32 * j];

    for (int d = 0; d < SDOCS; d++) {
        float dv[8];
        #pragma unroll
        for (int j = 0; j < 8; j++) dv[j] = das[d][lane + 32 * j];
        #pragma unroll
        for (int bi = 0; bi < 4; bi++) {
            int b = w + 8 * bi;
            const float* qrow = &qbs[b * Hc];
            float acc = 0.f;
            #pragma unroll
            for (int j = 0; j < 8; j++) {
                float x = qrow[lane + 32 * j] + dv[j];
                acc = fmaf(gelu_f(x), wv[j], acc);
            }
            #pragma unroll
            for (int o = 16; o; o >>= 1)
                acc += __shfl_down_sync(0xffffffffu, acc, o);
            if (lane == 0)
                g_scores[(size_t)b * N + docBase + d] = (acc + bb) * invt;
        }
    }
}

// ---------------------------------------------------------------------------
// Kernel 4: top-k + softmax.  grid = B, block = 256.
// Per-thread local top-k over strided scan, then serial merge by thread 0.
// Tie-break: equal values -> smaller index (matches jax.lax.top_k).
// ---------------------------------------------------------------------------
__global__ __launch_bounds__(256) void topk_kernel(
    const int* __restrict__ kptr, float* __restrict__ out, int N, int B)
{
    int b = blockIdx.x, t = threadIdx.x;
    int k = *kptr; if (k > KMAX) k = KMAX; if (k < 1) k = 1;

    float v[KMAX]; int id[KMAX];
    #pragma unroll
    for (int j = 0; j < KMAX; j++) { v[j] = -INFINITY; id[j] = 0x7fffffff; }
    float vmin = -INFINITY;
    const float* row = g_scores + (size_t)b * N;
    for (int i = t; i < N; i += 256) {
        float s = row[i];
        if (s > vmin) {
            int p = k - 1;
            while (p > 0 && (s > v[p - 1] || (s == v[p - 1] && i < id[p - 1]))) {
                v[p] = v[p - 1]; id[p] = id[p - 1]; p--;
            }
            v[p] = s; id[p] = i;
            vmin = v[k - 1];
        }
    }

    __shared__ float sv[256 * KMAX];
    __shared__ int   si[256 * KMAX];
    for (int j = 0; j < k; j++) { sv[t * KMAX + j] = v[j]; si[t * KMAX + j] = id[j]; }
    __syncthreads();

    if (t == 0) {
        float gv[KMAX]; int gi[KMAX];
        #pragma unroll
        for (int j = 0; j < KMAX; j++) { gv[j] = -INFINITY; gi[j] = 0x7fffffff; }
        for (int e = 0; e < 256; e++) {
            for (int j = 0; j < k; j++) {
                float s = sv[e * KMAX + j]; int ii = si[e * KMAX + j];
                if (s > gv[k - 1] || (s == gv[k - 1] && ii < gi[k - 1])) {
                    int p = k - 1;
                    while (p > 0 && (s > gv[p - 1] || (s == gv[p - 1] && ii < gi[p - 1]))) {
                        gv[p] = gv[p - 1]; gi[p] = gi[p - 1]; p--;
                    }
                    gv[p] = s; gi[p] = ii;
                }
            }
        }
        // softmax over top-k (gv sorted descending -> gv[0] is max)
        float mx = gv[0], sum = 0.f, ex[KMAX];
        for (int j = 0; j < k; j++) { ex[j] = expf(gv[j] - mx); sum += ex[j]; }
        float inv = 1.0f / sum;
        for (int j = 0; j < k; j++) {
            out[b * k + j] = (float)gi[j];            // top_idx (as float)
            out[B * k + b * k + j] = ex[j] * inv;     // probs
        }
    }
}

// ---------------------------------------------------------------------------
extern "C" void kernel_launch(void* const* d_in, const int* in_sizes, int n_in,
                              void* d_out, int out_size)
{
    const float* query = (const float*)d_in[0];
    const float* docs  = (const float*)d_in[1];
    const int*   kptr  = (const int*)d_in[2];
    const float* Wq    = (const float*)d_in[3];
    const float* bq    = (const float*)d_in[4];
    const float* lnqw  = (const float*)d_in[5];
    const float* lnqb  = (const float*)d_in[6];
    const float* Wd    = (const float*)d_in[7];
    const float* bd    = (const float*)d_in[8];
    const float* lndw  = (const float*)d_in[9];
    const float* lndb  = (const float*)d_in[10];
    const float* W1    = (const float*)d_in[11];
    const float* b1    = (const float*)d_in[12];
    const float* W2    = (const float*)d_in[13];
    const float* b2    = (const float*)d_in[14];
    const float* temp  = (const float*)d_in[15];

    int H = in_sizes[4];            // 256
    int Z = in_sizes[3] / H;        // 512
    int B = in_sizes[0] / Z;        // 32
    int N = in_sizes[1] / Z;        // 20000

    query_kernel<<<B, 256>>>(query, Wq, bq, lnqw, lnqb, W1, b1);
    doc_kernel<<<N / DPB, 256>>>(docs, Wd, bd, lndw, lndb, W1, N);
    score_kernel<<<N / SDOCS, 256>>>(W2, b2, temp, N);
    topk_kernel<<<B, 256>>>(kptr, (float*)d_out, N, B);
}

// round 2
// speedup vs baseline: 1.3828x; 1.3828x over previous
#include <cuda_runtime.h>
#include <math.h>

// Problem constants (fixed shapes for this problem instance)
#define Zc 512
#define Hc 256
#define NMAX 20000
#define BMAX 32
#define DPB 16     // docs per block in doc kernel
#define SDOCS 8    // docs per block in score kernel
#define KMAX 8

// Scratch (no allocations allowed anywhere)
__device__ float g_qb[BMAX * Hc];                 // qa + b1, [B,H]
__device__ float g_da[(size_t)NMAX * Hc];         // d_t @ W1[H:], [N,H]
__device__ float g_scores[(size_t)BMAX * NMAX];   // scaled scores [B,N]

__device__ __forceinline__ float gelu_f(float x) {
    // exact gelu: 0.5*x*(1+erf(x/sqrt(2)))
    return 0.5f * x * (1.0f + erff(x * 0.70710678118654752440f));
}

// ---------------------------------------------------------------------------
// Kernel 1: query path.  grid = B, block = 256 (one thread per h)
// q_t = LN(gelu(q@Wq + bq)); qb = q_t@W1[:H] + b1
// ---------------------------------------------------------------------------
__global__ __launch_bounds__(256) void query_kernel(
    const float* __restrict__ q, const float* __restrict__ Wq,
    const float* __restrict__ bq, const float* __restrict__ lnw,
    const float* __restrict__ lnb, const float* __restrict__ W1,
    const float* __restrict__ b1)
{
    __shared__ float xq[Zc];
    __shared__ float qt[Hc];
    __shared__ float red[18];
    int b = blockIdx.x, t = threadIdx.x;
    const float* row = q + (size_t)b * Zc;
    for (int i = t; i < Zc; i += 256) xq[i] = row[i];
    __syncthreads();

    float acc = bq[t];
    #pragma unroll 8
    for (int z = 0; z < Zc; z++) acc = fmaf(xq[z], Wq[z * Hc + t], acc);
    float g = gelu_f(acc);

    float s = g, s2 = g * g;
    #pragma unroll
    for (int o = 16; o; o >>= 1) {
        s  += __shfl_down_sync(0xffffffffu, s, o);
        s2 += __shfl_down_sync(0xffffffffu, s2, o);
    }
    if ((t & 31) == 0) { red[t >> 5] = s; red[8 + (t >> 5)] = s2; }
    __syncthreads();
    if (t == 0) {
        float S = 0.f, S2 = 0.f;
        for (int w = 0; w < 8; w++) { S += red[w]; S2 += red[8 + w]; }
        float mu = S / (float)Hc;
        red[16] = mu;
        red[17] = S2 / (float)Hc - mu * mu;
    }
    __syncthreads();
    float mu = red[16], var = red[17];
    float v = (g - mu) * rsqrtf(var + 1e-5f) * lnw[t] + lnb[t];
    qt[t] = v;
    __syncthreads();

    float a2 = b1[t];  // fold b1 here
    #pragma unroll 8
    for (int j = 0; j < Hc; j++) a2 = fmaf(qt[j], W1[j * Hc + t], a2);
    g_qb[b * Hc + t] = a2;
}

// ---------------------------------------------------------------------------
// Kernel 2: doc path, fused. grid = N/DPB, block = 256.
// hg = tid&63 owns h = 4*hg..4*hg+3 (float4); ds = tid>>6 owns docs
// {ds, ds+4, ds+8, ds+12}. d_t never leaves smem; only da is written.
// ---------------------------------------------------------------------------
__global__ __launch_bounds__(256) void doc_kernel(
    const float* __restrict__ docs, const float* __restrict__ Wd,
    const float* __restrict__ bd, const float* __restrict__ lnw,
    const float* __restrict__ lnb, const float* __restrict__ W1, int N)
{
    __shared__ float xs[DPB][Zc];   // 32 KB: raw doc rows
    __shared__ float dt[DPB][Hc];   // 16 KB: post-gelu / post-LN activations
    int t = threadIdx.x;
    int hg = t & 63, ds = t >> 6;
    int docBase = blockIdx.x * DPB;

    const float4* src = (const float4*)(docs + (size_t)docBase * Zc);
    float4* dstp = (float4*)&xs[0][0];
    #pragma unroll
    for (int i = t; i < DPB * Zc / 4; i += 256) dstp[i] = src[i];
    __syncthreads();

    // GEMM1: d = x @ Wd + bd  (each thread: 4h x 4docs)
    float4 bd4 = *(const float4*)&bd[hg * 4];
    float4 a0 = bd4, a1 = bd4, a2 = bd4, a3 = bd4;
    for (int z = 0; z < Zc; z += 4) {
        float4 x0 = *(const float4*)&xs[ds][z];
        float4 x1 = *(const float4*)&xs[ds + 4][z];
        float4 x2 = *(const float4*)&xs[ds + 8][z];
        float4 x3 = *(const float4*)&xs[ds + 12][z];
        float x0v[4] = {x0.x, x0.y, x0.z, x0.w};
        float x1v[4] = {x1.x, x1.y, x1.z, x1.w};
        float x2v[4] = {x2.x, x2.y, x2.z, x2.w};
        float x3v[4] = {x3.x, x3.y, x3.z, x3.w};
        #pragma unroll
        for (int u = 0; u < 4; u++) {
            float4 w = *(const float4*)&Wd[(size_t)(z + u) * Hc + hg * 4];
            a0.x = fmaf(w.x, x0v[u], a0.x); a0.y = fmaf(w.y, x0v[u], a0.y);
            a0.z = fmaf(w.z, x0v[u], a0.z); a0.w = fmaf(w.w, x0v[u], a0.w);
            a1.x = fmaf(w.x, x1v[u], a1.x); a1.y = fmaf(w.y, x1v[u], a1.y);
            a1.z = fmaf(w.z, x1v[u], a1.z); a1.w = fmaf(w.w, x1v[u], a1.w);
            a2.x = fmaf(w.x, x2v[u], a2.x); a2.y = fmaf(w.y, x2v[u], a2.y);
            a2.z = fmaf(w.z, x2v[u], a2.z); a2.w = fmaf(w.w, x2v[u], a2.w);
            a3.x = fmaf(w.x, x3v[u], a3.x); a3.y = fmaf(w.y, x3v[u], a3.y);
            a3.z = fmaf(w.z, x3v[u], a3.z); a3.w = fmaf(w.w, x3v[u], a3.w);
        }
    }
    dt[ds][hg * 4 + 0] = gelu_f(a0.x); dt[ds][hg * 4 + 1] = gelu_f(a0.y);
    dt[ds][hg * 4 + 2] = gelu_f(a0.z); dt[ds][hg * 4 + 3] = gelu_f(a0.w);
    dt[ds + 4][hg * 4 + 0] = gelu_f(a1.x); dt[ds + 4][hg * 4 + 1] = gelu_f(a1.y);
    dt[ds + 4][hg * 4 + 2] = gelu_f(a1.z); dt[ds + 4][hg * 4 + 3] = gelu_f(a1.w);
    dt[ds + 8][hg * 4 + 0] = gelu_f(a2.x); dt[ds + 8][hg * 4 + 1] = gelu_f(a2.y);
    dt[ds + 8][hg * 4 + 2] = gelu_f(a2.z); dt[ds + 8][hg * 4 + 3] = gelu_f(a2.w);
    dt[ds + 12][hg * 4 + 0] = gelu_f(a3.x); dt[ds + 12][hg * 4 + 1] = gelu_f(a3.y);
    dt[ds + 12][hg * 4 + 2] = gelu_f(a3.z); dt[ds + 12][hg * 4 + 3] = gelu_f(a3.w);
    __syncthreads();

    // LayerNorm per doc: warp w normalizes docs 2w, 2w+1
    {
        int wid = t >> 5, lane = t & 31;
        #pragma unroll
        for (int dd = 0; dd < 2; dd++) {
            float* r = dt[wid * 2 + dd];
            float s = 0.f, s2 = 0.f;
            #pragma unroll
            for (int j = lane; j < Hc; j += 32) { float v = r[j]; s += v; s2 += v * v; }
            #pragma unroll
            for (int o = 16; o; o >>= 1) {
                s  += __shfl_xor_sync(0xffffffffu, s, o);
                s2 += __shfl_xor_sync(0xffffffffu, s2, o);
            }
            float mu = s / (float)Hc;
            float rin = rsqrtf(s2 / (float)Hc - mu * mu + 1e-5f);
            #pragma unroll
            for (int j = lane; j < Hc; j += 32)
                r[j] = (r[j] - mu) * rin * lnw[j] + lnb[j];
        }
    }
    __syncthreads();

    // GEMM2: da = dt @ W1[H:2H]
    float4 c0 = make_float4(0.f,0.f,0.f,0.f), c1 = c0, c2 = c0, c3 = c0;
    for (int j = 0; j < Hc; j += 4) {
        float4 x0 = *(const float4*)&dt[ds][j];
        float4 x1 = *(const float4*)&dt[ds + 4][j];
        float4 x2 = *(const float4*)&dt[ds + 8][j];
        float4 x3 = *(const float4*)&dt[ds + 12][j];
        float x0v[4] = {x0.x, x0.y, x0.z, x0.w};
        float x1v[4] = {x1.x, x1.y, x1.z, x1.w};
        float x2v[4] = {x2.x, x2.y, x2.z, x2.w};
        float x3v[4] = {x3.x, x3.y, x3.z, x3.w};
        #pragma unroll
        for (int u = 0; u < 4; u++) {
            float4 w = *(const float4*)&W1[(size_t)(Hc + j + u) * Hc + hg * 4];
            c0.x = fmaf(w.x, x0v[u], c0.x); c0.y = fmaf(w.y, x0v[u], c0.y);
            c0.z = fmaf(w.z, x0v[u], c0.z); c0.w = fmaf(w.w, x0v[u], c0.w);
            c1.x = fmaf(w.x, x1v[u], c1.x); c1.y = fmaf(w.y, x1v[u], c1.y);
            c1.z = fmaf(w.z, x1v[u], c1.z); c1.w = fmaf(w.w, x1v[u], c1.w);
            c2.x = fmaf(w.x, x2v[u], c2.x); c2.y = fmaf(w.y, x2v[u], c2.y);
            c2.z = fmaf(w.z, x2v[u], c2.z); c2.w = fmaf(w.w, x2v[u], c2.w);
            c3.x = fmaf(w.x, x3v[u], c3.x); c3.y = fmaf(w.y, x3v[u], c3.y);
            c3.z = fmaf(w.z, x3v[u], c3.z); c3.w = fmaf(w.w, x3v[u], c3.w);
        }
    }
    ((float4*)&g_da[(size_t)(docBase + ds) * Hc])[hg] = c0;
    ((float4*)&g_da[(size_t)(docBase + ds + 4) * Hc])[hg] = c1;
    ((float4*)&g_da[(size_t)(docBase + ds + 8) * Hc])[hg] = c2;
    ((float4*)&g_da[(size_t)(docBase + ds + 12) * Hc])[hg] = c3;
}

// ---------------------------------------------------------------------------
// Kernel 3: pairwise scoring.  grid = N/SDOCS, block = 256.
// raw[b,n] = sum_h gelu(qb[b,h] + da[n,h]) * W2[h] + b2;  scaled by 1/(|T|+eps)
// Warp w handles b in {w, w+8, w+16, w+24}; lane owns 8 h-slots; q-values
// hoisted to registers and reused across all 8 docs.
// ---------------------------------------------------------------------------
__global__ __launch_bounds__(256) void score_kernel(
    const float* __restrict__ W2, const float* __restrict__ b2,
    const float* __restrict__ temp, int N)
{
    __shared__ float qbs[BMAX * Hc];   // 32 KB
    __shared__ float das[SDOCS][Hc];   // 8 KB
    __shared__ float w2s[Hc];
    int t = threadIdx.x;

    const float4* qsrc = (const float4*)g_qb;
    float4* qdst = (float4*)qbs;
    #pragma unroll
    for (int i = t; i < BMAX * Hc / 4; i += 256) qdst[i] = qsrc[i];
    w2s[t] = W2[t];
    int docBase = blockIdx.x * SDOCS;
    {
        const float4* dsrc = (const float4*)(g_da + (size_t)docBase * Hc);
        float4* ddst = (float4*)&das[0][0];
        ddst[t] = dsrc[t];
        ddst[t + 256] = dsrc[t + 256];
    }
    __syncthreads();

    float invt = 1.0f / (fabsf(temp[0]) + 1e-8f);
    float bb = b2[0];
    int w = t >> 5, lane = t & 31;

    float wv[8];
    #pragma unroll
    for (int j = 0; j < 8; j++) wv[j] = w2s[lane + 32 * j];

    #pragma unroll
    for (int bi = 0; bi < 4; bi++) {
        int b = w + 8 * bi;
        const float* qrow = &qbs[b * Hc];
        float qv[8];
        #pragma unroll
        for (int j = 0; j < 8; j++) qv[j] = qrow[lane + 32 * j];
        #pragma unroll
        for (int d = 0; d < SDOCS; d++) {
            float acc = 0.f;
            #pragma unroll
            for (int j = 0; j < 8; j++) {
                float x = qv[j] + das[d][lane + 32 * j];
                acc = fmaf(gelu_f(x), wv[j], acc);
            }
            #pragma unroll
            for (int o = 16; o; o >>= 1)
                acc += __shfl_down_sync(0xffffffffu, acc, o);
            if (lane == 0)
                g_scores[(size_t)b * N + docBase + d] = (acc + bb) * invt;
        }
    }
}

// ---------------------------------------------------------------------------
// Kernel 4: top-k + softmax.  grid = B, block = 256.
// (score, index) packed into one orderable uint64 key; per-thread top-8 held
// SORTED IN REGISTERS via unrolled compare-swap (no local memory); block merge
// = k rounds of parallel argmax over the 2048 candidates in shared.
// Tie-break: equal score -> smaller index (key low word = ~index).
// ---------------------------------------------------------------------------
__device__ __forceinline__ unsigned long long pack_key(float s, int i) {
    unsigned int u = __float_as_uint(s);
    u = (u & 0x80000000u) ? ~u : (u | 0x80000000u);
    return ((unsigned long long)u << 32) | (unsigned int)(~(unsigned int)i);
}

__global__ __launch_bounds__(256) void topk_kernel(
    const int* __restrict__ kptr, float* __restrict__ out, int N, int B)
{
    __shared__ unsigned long long sk[256 * KMAX];   // 16 KB
    __shared__ unsigned long long warpmax[8];
    __shared__ unsigned long long bestsh;

    int b = blockIdx.x, t = threadIdx.x;
    int k = *kptr; if (k > KMAX) k = KMAX; if (k < 1) k = 1;

    unsigned long long loc[KMAX];
    #pragma unroll
    for (int j = 0; j < KMAX; j++) loc[j] = 0ull;

    const float* row = g_scores + (size_t)b * N;
    for (int i = t; i < N; i += 256) {
        unsigned long long key = pack_key(row[i], i);
        if (key > loc[KMAX - 1]) {
            #pragma unroll
            for (int j = 0; j < KMAX; j++) {
                unsigned long long cur = loc[j];
                bool gt = key > cur;
                loc[j] = gt ? key : cur;
                key    = gt ? cur : key;
            }
        }
    }
    #pragma unroll
    for (int j = 0; j < KMAX; j++) sk[t * KMAX + j] = loc[j];
    __syncthreads();

    unsigned long long keys[KMAX];
    int wlane = t & 31, wid = t >> 5;
    for (int r = 0; r < k; r++) {
        unsigned long long m = 0ull;
        #pragma unroll
        for (int j = 0; j < KMAX; j++) {
            unsigned long long v = sk[t * KMAX + j];
            m = (v > m) ? v : m;
        }
        #pragma unroll
        for (int o = 16; o; o >>= 1) {
            unsigned long long v = __shfl_xor_sync(0xffffffffu, m, o);
            m = (v > m) ? v : m;
        }
        if (wlane == 0) warpmax[wid] = m;
        __syncthreads();
        if (t == 0) {
            unsigned long long best = 0ull;
            #pragma unroll
            for (int ww = 0; ww < 8; ww++)
                best = (warpmax[ww] > best) ? warpmax[ww] : best;
            bestsh = best;
        }
        __syncthreads();
        unsigned long long best = bestsh;
        if (t == 0) keys[r] = best;
        #pragma unroll
        for (int j = 0; j < KMAX; j++)
            if (sk[t * KMAX + j] == best) sk[t * KMAX + j] = 0ull;
        __syncthreads();
    }

    if (t == 0) {
        float gv[KMAX]; int gi[KMAX];
        for (int r = 0; r < k; r++) {
            unsigned int hi = (unsigned int)(keys[r] >> 32);
            unsigned int u = (hi & 0x80000000u) ? (hi ^ 0x80000000u) : ~hi;
            gv[r] = __uint_as_float(u);
            gi[r] = (int)(~(unsigned int)(keys[r] & 0xffffffffu));
        }
        float mx = gv[0], sum = 0.f, ex[KMAX];
        for (int j = 0; j < k; j++) { ex[j] = expf(gv[j] - mx); sum += ex[j]; }
        float inv = 1.0f / sum;
        for (int j = 0; j < k; j++) {
            out[b * k + j] = (float)gi[j];            // top_idx (as float)
            out[B * k + b * k + j] = ex[j] * inv;     // probs
        }
    }
}

// ---------------------------------------------------------------------------
extern "C" void kernel_launch(void* const* d_in, const int* in_sizes, int n_in,
                              void* d_out, int out_size)
{
    const float* query = (const float*)d_in[0];
    const float* docs  = (const float*)d_in[1];
    const int*   kptr  = (const int*)d_in[2];
    const float* Wq    = (const float*)d_in[3];
    const float* bq    = (const float*)d_in[4];
    const float* lnqw  = (const float*)d_in[5];
    const float* lnqb  = (const float*)d_in[6];
    const float* Wd    = (const float*)d_in[7];
    const float* bd    = (const float*)d_in[8];
    const float* lndw  = (const float*)d_in[9];
    const float* lndb  = (const float*)d_in[10];
    const float* W1    = (const float*)d_in[11];
    const float* b1    = (const float*)d_in[12];
    const float* W2    = (const float*)d_in[13];
    const float* b2    = (const float*)d_in[14];
    const float* temp  = (const float*)d_in[15];

    int H = in_sizes[4];            // 256
    int Z = in_sizes[3] / H;        // 512
    int B = in_sizes[0] / Z;        // 32
    int N = in_sizes[1] / Z;        // 20000

    query_kernel<<<B, 256>>>(query, Wq, bq, lnqw, lnqb, W1, b1);
    doc_kernel<<<N / DPB, 256>>>(docs, Wd, bd, lndw, lndb, W1, N);
    score_kernel<<<N / SDOCS, 256>>>(W2, b2, temp, N);
    topk_kernel<<<B, 256>>>(kptr, (float*)d_out, N, B);
}